// round 15
// baseline (speedup 1.0000x reference)
#include <cuda_runtime.h>
#include <cuda_fp16.h>
#include <math.h>
#include <stdint.h>

// Problem constants
#define LSEQ 700
#define BATCH 32
#define DIN 41
#define HID 800
#define GATES 3200          // 4*HID
#define H2 1600             // 2*HID
#define NCOORD 2100         // 3*LSEQ

// ---------------- device scratch (allocation-free rule: __device__ globals) ---
__device__ float g_G0[2L * LSEQ * GATES * BATCH];   // [2][700][3200][32]
__device__ float g_G1[2L * LSEQ * GATES * BATCH];
__device__ float g_h1[LSEQ * H2 * BATCH];           // layer-1 h (fp32, for head)
__device__ float g_ang[LSEQ * BATCH * 3];
__device__ unsigned g_cnt[4];
__device__ unsigned g_ack[4];
// fp16 operands
__device__ unsigned short g_Ahi16[22400L * 1600];   // h0 fp16 [row=t*32+b][k]
__device__ unsigned g_Bhi[6400 * 800];              // Wih1 fp16 [col][k/2]
__device__ unsigned g_X16[22400L * 24];             // x fp16 [row][k/2] (K=41->48)
__device__ unsigned g_B016[6400 * 24];              // Wih0 fp16 [col][k/2]
// fp16 h state for recurrence MMA: [dir][batch][k]
__device__ unsigned short g_hbf16[2 * 32 * 800];

// ---------------- fp16 helpers -------------------------------------------------
__device__ __forceinline__ unsigned packh2(float a, float b)
{
    __half2 h = __floats2half2_rn(a, b);
    return *(unsigned*)&h;
}
__device__ __forceinline__ void st_u16_cg(unsigned short* p, unsigned short v)
{
    asm volatile("st.global.cg.u16 [%0], %1;" :: "l"(p), "h"(v) : "memory");
}
__device__ __forceinline__ float sigf(float x) { return 1.f / (1.f + expf(-x)); }

// ---------------- warp MMA fp16 ------------------------------------------------
__device__ __forceinline__ void mma16816h(float* d, const unsigned* a,
                                          const unsigned* b)
{
    asm volatile(
        "mma.sync.aligned.m16n8k16.row.col.f32.f16.f16.f32 "
        "{%0,%1,%2,%3}, {%4,%5,%6,%7}, {%8,%9}, {%0,%1,%2,%3};"
        : "+f"(d[0]), "+f"(d[1]), "+f"(d[2]), "+f"(d[3])
        : "r"(a[0]), "r"(a[1]), "r"(a[2]), "r"(a[3]), "r"(b[0]), "r"(b[1]));
}

// =============================================================================
// conv_x: x [32][700][41] f32 -> g_X16 [row=t*32+b][kp<24] fp16 pairs (pad 48).
// =============================================================================
__global__ __launch_bounds__(256)
void conv_x(const float* __restrict__ x)
{
    long i = (long)blockIdx.x * 256 + threadIdx.x;
    if (i >= 22400L * 24) return;
    int row = (int)(i / 24), kp = (int)(i % 24);
    int t = row >> 5, b = row & 31;
    int k0 = 2 * kp, k1 = 2 * kp + 1;
    float v0 = (k0 < DIN) ? x[((long)b * LSEQ + t) * DIN + k0] : 0.f;
    float v1 = (k1 < DIN) ? x[((long)b * LSEQ + t) * DIN + k1] : 0.f;
    g_X16[i] = packh2(v0, v1);
}

// =============================================================================
// conv_w0: Wih0 [2][3200][41] f32 -> g_B016 [col=dir*3200+j][kp<24] fp16 pairs.
// =============================================================================
__global__ __launch_bounds__(256)
void conv_w0(const float* __restrict__ W)
{
    long i = (long)blockIdx.x * 256 + threadIdx.x;
    if (i >= 6400L * 24) return;
    int col = (int)(i / 24), kp = (int)(i % 24);
    int k0 = 2 * kp, k1 = 2 * kp + 1;
    float v0 = (k0 < DIN) ? W[(long)col * DIN + k0] : 0.f;
    float v1 = (k1 < DIN) ? W[(long)col * DIN + k1] : 0.f;
    g_B016[i] = packh2(v0, v1);
}

// =============================================================================
// conv_w: Wih1 [6400][1600] f32 -> fp16 packed pairs [6400][800].
// =============================================================================
__global__ __launch_bounds__(256)
void conv_w(const float* __restrict__ W)
{
    long i = (long)blockIdx.x * 256 + threadIdx.x;
    if (i >= 6400L * 800) return;
    float2 v = *(const float2*)(W + 2 * i);
    g_Bhi[i] = packh2(v.x, v.y);
}

// =============================================================================
// gemm0_mma: G0 = x @ Wih0^T + biases via fp16 warp MMA (K=48, one chunk).
// Grid (50 col-tiles x 175 row-tiles), 256 threads = 8 warps.
// =============================================================================
#define M0STR 28
__global__ __launch_bounds__(256, 2)
void gemm0_mma(const float* __restrict__ bias1, const float* __restrict__ bias2,
               float* __restrict__ Gout)
{
    __shared__ unsigned As[128 * M0STR];
    __shared__ unsigned Bs[128 * M0STR];

    int tid = threadIdx.x;
    int wid = tid >> 5, lane = tid & 31;
    int g = lane >> 2, tig = lane & 3;
    int col0 = blockIdx.x * 128;
    int row0 = blockIdx.y * 128;
    int m0 = (wid & 3) * 32;
    int n0 = (wid >> 2) * 64;

    for (int i = tid; i < 128 * 24; i += 256) {
        int r = i / 24, kp = i % 24;
        As[r * M0STR + kp] = g_X16[(long)(row0 + r) * 24 + kp];
        Bs[r * M0STR + kp] = g_B016[(long)(col0 + r) * 24 + kp];
    }
    __syncthreads();

    float acc[2][8][4];
#pragma unroll
    for (int mt = 0; mt < 2; mt++)
#pragma unroll
        for (int nt = 0; nt < 8; nt++)
#pragma unroll
            for (int q = 0; q < 4; q++) acc[mt][nt][q] = 0.f;

#pragma unroll
    for (int kk = 0; kk < 3; kk++) {
        int kpb = kk * 8;
        unsigned bh[8][2];
#pragma unroll
        for (int nt = 0; nt < 8; nt++) {
            int br = (n0 + nt * 8 + g) * M0STR + kpb + tig;
            bh[nt][0] = Bs[br];     bh[nt][1] = Bs[br + 4];
        }
#pragma unroll
        for (int mt = 0; mt < 2; mt++) {
            int ar0 = (m0 + mt * 16 + g) * M0STR + kpb + tig;
            int ar1 = ar0 + 8 * M0STR;
            unsigned ah[4] = { As[ar0], As[ar1], As[ar0 + 4], As[ar1 + 4] };
#pragma unroll
            for (int nt = 0; nt < 8; nt++)
                mma16816h(acc[mt][nt], ah, bh[nt]);
        }
    }

#pragma unroll
    for (int mt = 0; mt < 2; mt++) {
        int r0 = row0 + m0 + mt * 16 + g;
        int r1 = r0 + 8;
        int t0 = r0 >> 5, b0 = r0 & 31;
        int t1 = r1 >> 5, b1 = r1 & 31;
#pragma unroll
        for (int nt = 0; nt < 8; nt++) {
            int c0 = col0 + n0 + nt * 8 + 2 * tig;
#pragma unroll
            for (int q = 0; q < 2; q++) {
                int col = c0 + q;
                int dir = (col >= GATES) ? 1 : 0;
                int j = col - dir * GATES;
                float bb = bias1[col] + bias2[col];
                Gout[((long)(dir * LSEQ + t0) * GATES + j) * BATCH + b0] =
                    acc[mt][nt][q] + bb;
                Gout[((long)(dir * LSEQ + t1) * GATES + j) * BATCH + b1] =
                    acc[mt][nt][2 + q] + bb;
            }
        }
    }
}

// =============================================================================
// gemm1_mma: G1 = h0 @ Wih1^T + biases via pure fp16 warp MMA (unchanged R14).
// =============================================================================
#define MM_STRIDE 36
#define MM_ASZ (128 * MM_STRIDE)
#define MM_SMEM (2 * MM_ASZ * 4)                    // 36864 bytes

__global__ __launch_bounds__(256, 2)
void gemm1_mma(const float* __restrict__ bias1, const float* __restrict__ bias2,
               float* __restrict__ Gout)
{
    extern __shared__ unsigned sm[];
    unsigned* Ah = sm;
    unsigned* Bh = Ah + MM_ASZ;

    const unsigned* Asrc = (const unsigned*)g_Ahi16;

    int tid = threadIdx.x;
    int wid = tid >> 5, lane = tid & 31;
    int g = lane >> 2, tig = lane & 3;
    int col0 = blockIdx.x * 128;
    int row0 = blockIdx.y * 128;
    int m0 = (wid & 3) * 32;
    int n0 = (wid >> 2) * 64;

    float acc[2][8][4];
#pragma unroll
    for (int mt = 0; mt < 2; mt++)
#pragma unroll
        for (int nt = 0; nt < 8; nt++)
#pragma unroll
            for (int q = 0; q < 4; q++) acc[mt][nt][q] = 0.f;

    int sr = tid >> 4, skq = tid & 15;

    for (int ch = 0; ch < 25; ch++) {
        __syncthreads();
#pragma unroll
        for (int it = 0; it < 8; it++) {
            int rr = sr + it * 16;
            long ao = (long)(row0 + rr) * 800 + ch * 32 + 2 * skq;
            long bo = (long)(col0 + rr) * 800 + ch * 32 + 2 * skq;
            *(uint2*)(Ah + rr * MM_STRIDE + 2 * skq) = *(const uint2*)(Asrc + ao);
            *(uint2*)(Bh + rr * MM_STRIDE + 2 * skq) = *(const uint2*)(g_Bhi + bo);
        }
        __syncthreads();

#pragma unroll
        for (int kk = 0; kk < 4; kk++) {
            int kpb = kk * 8;
            unsigned bh[8][2];
#pragma unroll
            for (int nt = 0; nt < 8; nt++) {
                int br = (n0 + nt * 8 + g) * MM_STRIDE + kpb + tig;
                bh[nt][0] = Bh[br];     bh[nt][1] = Bh[br + 4];
            }
#pragma unroll
            for (int mt = 0; mt < 2; mt++) {
                int ar0 = (m0 + mt * 16 + g) * MM_STRIDE + kpb + tig;
                int ar1 = ar0 + 8 * MM_STRIDE;
                unsigned ah[4] = { Ah[ar0], Ah[ar1], Ah[ar0 + 4], Ah[ar1 + 4] };
#pragma unroll
                for (int nt = 0; nt < 8; nt++)
                    mma16816h(acc[mt][nt], ah, bh[nt]);
            }
        }
    }

#pragma unroll
    for (int mt = 0; mt < 2; mt++) {
        int r0 = row0 + m0 + mt * 16 + g;
        int r1 = r0 + 8;
        int t0 = r0 >> 5, b0 = r0 & 31;
        int t1 = r1 >> 5, b1 = r1 & 31;
#pragma unroll
        for (int nt = 0; nt < 8; nt++) {
            int c0 = col0 + n0 + nt * 8 + 2 * tig;
#pragma unroll
            for (int q = 0; q < 2; q++) {
                int col = c0 + q;
                int dir = (col >= GATES) ? 1 : 0;
                int j = col - dir * GATES;
                float bb = bias1[col] + bias2[col];
                Gout[((long)(dir * LSEQ + t0) * GATES + j) * BATCH + b0] =
                    acc[mt][nt][q] + bb;
                Gout[((long)(dir * LSEQ + t1) * GATES + j) * BATCH + b1] =
                    acc[mt][nt][2 + q] + bb;
            }
        }
    }
}

// =============================================================================
// Persistent bidirectional LSTM recurrence — pure fp16 MMA, 512 threads.
// R15: uint4 h staging, G(s+1) prefetch before the grid barrier, one fewer
// syncthreads per step. Otherwise identical to passing R14.
// =============================================================================
#define NCTA_DIR 50
#define WSTR 404
#define LS_WW (64 * WSTR)
#define LS_BS_OFF (LS_WW * 4)                   // 103424
#define LS_BW (32 * WSTR)
#define LS_PB_OFF (LS_BS_OFF + LS_BW * 4)       // 155136
#define SMEM_LSTM (LS_PB_OFF + 2 * 64 * 32 * 4) // 171520 bytes

__global__ __launch_bounds__(512, 1)
void lstm_persist(const float* __restrict__ Whh, int layer)
{
    extern __shared__ char smemc[];
    unsigned* wsH = (unsigned*)smemc;                  // [64][WSTR] fp16 pairs
    unsigned* bs  = (unsigned*)(smemc + LS_BS_OFF);    // [32][WSTR] fp16 h pairs
    float* pb = (float*)(smemc + LS_PB_OFF);           // [2][64][32]

    const float* G = layer ? g_G1 : g_G0;

    int c   = blockIdx.x;
    int dir = c / NCTA_DIR;
    int ubase = (c % NCTA_DIR) * 16;
    int tid = threadIdx.x;
    int wid = tid >> 5, lane = tid & 31;
    int gate  = wid & 3;
    int khalf = (wid >> 2) & 1;
    int nhalf = wid >> 3;
    int g = lane >> 2, tig = lane & 3;
    int cb = lane;
    int lu = wid;
    int u  = ubase + lu;

    unsigned short* hb16 = g_hbf16 + dir * 32 * 800;   // [32][800]
    const uint4* hb4 = (const uint4*)hb16;             // 3200 uint4

    unsigned* cnt = &g_cnt[layer * 2 + dir];
    unsigned* ack = &g_ack[layer * 2 + dir];

    // ---- convert Whh slice -> smem fp16 (once) ----
    const float* Wd = Whh + (long)dir * GATES * HID;
    for (int i = tid; i < 64 * 400; i += 512) {
        int r = i / 400, kp = i % 400;
        int grow = (r >> 4) * HID + ubase + (r & 15);
        float v0 = Wd[(long)grow * HID + 2 * kp];
        float v1 = Wd[(long)grow * HID + 2 * kp + 1];
        wsH[r * WSTR + kp] = packh2(v0, v1);
    }
    __syncthreads();

    float creg = 0.f;

    // prefetch G for s=0
    float gpn[4];
    {
        int t0i = dir ? (LSEQ - 1) : 0;
        long gb = ((long)(dir * LSEQ + t0i)) * GATES * BATCH;
#pragma unroll
        for (int g4 = 0; g4 < 4; g4++)
            gpn[g4] = G[gb + (long)(g4 * HID + u) * BATCH + cb];
    }

    for (int s = 0; s < LSEQ; s++) {
        int t = dir ? (LSEQ - 1 - s) : s;

        float gp[4] = { gpn[0], gpn[1], gpn[2], gpn[3] };
        float ds[4] = { 0.f, 0.f, 0.f, 0.f };

        if (s > 0) {
            // stage FULL h via uint4 (bs free: guaranteed by prev step's syncs)
            for (int i = tid; i < 3200; i += 512) {
                int b = i / 100, q = i - b * 100;
                uint4 v;
                asm volatile("ld.global.cg.v4.u32 {%0,%1,%2,%3}, [%4];"
                             : "=r"(v.x), "=r"(v.y), "=r"(v.z), "=r"(v.w)
                             : "l"(hb4 + i));
                *(uint4*)(bs + b * WSTR + 4 * q) = v;
            }
            __syncthreads();                           // bs ready

            float acc[2][4];
#pragma unroll
            for (int ntl = 0; ntl < 2; ntl++)
#pragma unroll
                for (int q = 0; q < 4; q++) acc[ntl][q] = 0.f;

#pragma unroll
            for (int ki = 0; ki < 25; ki++) {
                int kk = khalf * 25 + ki;
                int akp = kk * 8 + tig;
                int ar0 = (gate * 16 + g) * WSTR + akp;
                int ar1 = ar0 + 8 * WSTR;
                unsigned ah[4] = { wsH[ar0], wsH[ar1], wsH[ar0+4], wsH[ar1+4] };
#pragma unroll
                for (int ntl = 0; ntl < 2; ntl++) {
                    int nt = nhalf * 2 + ntl;
                    int br = (nt * 8 + g) * WSTR + akp;
                    unsigned bfr[2] = { bs[br], bs[br + 4] };
                    mma16816h(acc[ntl], ah, bfr);
                }
            }

            {
                float* pbW = pb + khalf * (64 * 32);
#pragma unroll
                for (int ntl = 0; ntl < 2; ntl++) {
                    int colb = (nhalf * 2 + ntl) * 8 + 2 * tig;
                    pbW[(gate * 16 + g) * 32 + colb]         = acc[ntl][0];
                    pbW[(gate * 16 + g) * 32 + colb + 1]     = acc[ntl][1];
                    pbW[(gate * 16 + g + 8) * 32 + colb]     = acc[ntl][2];
                    pbW[(gate * 16 + g + 8) * 32 + colb + 1] = acc[ntl][3];
                }
            }
            __syncthreads();                           // pb ready
#pragma unroll
            for (int g4 = 0; g4 < 4; g4++) {
                int r = (g4 * 16 + lu) * 32 + cb;
                ds[g4] = pb[r] + pb[64 * 32 + r];
            }
        }

        // ---- LSTM cell (one unit) ----
        float ai = gp[0] + ds[0];
        float af = gp[1] + ds[1];
        float ag = gp[2] + ds[2];
        float ao = gp[3] + ds[3];

        creg = sigf(af) * creg + sigf(ai) * tanhf(ag);
        float hv = sigf(ao) * tanhf(creg);

        if (layer) {
            __stcg(g_h1 + ((long)t * H2 + dir * HID + u) * BATCH + cb, hv);
        } else {
            st_u16_cg(g_Ahi16 + ((long)(t * 32 + cb) * 1600 + dir * 800 + u),
                      __half_as_ushort(__float2half_rn(hv)));
        }
        st_u16_cg(hb16 + cb * 800 + u, __half_as_ushort(__float2half_rn(hv)));

        // ---- prefetch G for s+1 (hidden under barrier wait) ----
        if (s + 1 < LSEQ) {
            int tn = dir ? (LSEQ - 2 - s) : (s + 1);
            long gbn = ((long)(dir * LSEQ + tn)) * GATES * BATCH;
#pragma unroll
            for (int g4 = 0; g4 < 4; g4++)
                gpn[g4] = G[gbn + (long)(g4 * HID + u) * BATCH + cb];
        }

        // ---- grid barrier over this direction's 50 CTAs ----
        __syncthreads();
        if (tid == 0) {
            asm volatile("red.release.gpu.global.add.u32 [%0], %1;"
                         :: "l"(cnt), "r"(1u) : "memory");
            unsigned target = (unsigned)(s + 1) * NCTA_DIR;
            unsigned v;
            do {
                asm volatile("ld.acquire.gpu.global.u32 %0, [%1];"
                             : "=r"(v) : "l"(cnt) : "memory");
            } while (v < target);
        }
        __syncthreads();
    }

    // ---- replay-safe counter reset via ack ----
    if (tid == 0) {
        asm volatile("red.release.gpu.global.add.u32 [%0], %1;"
                     :: "l"(ack), "r"(1u) : "memory");
        if ((c % NCTA_DIR) == 0) {
            unsigned v;
            do {
                asm volatile("ld.acquire.gpu.global.u32 %0, [%1];"
                             : "=r"(v) : "l"(ack) : "memory");
            } while (v < NCTA_DIR);
            *cnt = 0;
            *ack = 0;
            __threadfence();
        }
    }
}

// =============================================================================
// Fused head (k-chunk 160): linear -> softmax over BATCH dim -> angles.
// =============================================================================
#define HCHUNK 160
__global__ __launch_bounds__(640)
void head_kernel(const float* __restrict__ wlin, const float* __restrict__ blin,
                 const float* __restrict__ alphabet)
{
    int l = blockIdx.x;
    int tid = threadIdx.x;
    int j = tid >> 5, b = tid & 31;

    __shared__ float hs[HCHUNK * 32];
    __shared__ float ps[20][32];
    __shared__ float sa[60], ca[60];

    if (tid < 60) { float v = alphabet[tid]; sa[tid] = sinf(v); ca[tid] = cosf(v); }

    float acc = blin[j];
    const float* hb = g_h1 + (long)l * (H2 * BATCH);
    const float* w = wlin + j * H2;
    for (int k0 = 0; k0 < H2; k0 += HCHUNK) {
        __syncthreads();
#pragma unroll
        for (int i = 0; i < (HCHUNK * 32) / 640; i++)
            hs[tid + 640 * i] = hb[k0 * 32 + tid + 640 * i];
        __syncthreads();
#pragma unroll 8
        for (int k = 0; k < HCHUNK; k += 4) {
            float4 w4 = *(const float4*)(w + k0 + k);
            acc += w4.x * hs[(k + 0) * 32 + b];
            acc += w4.y * hs[(k + 1) * 32 + b];
            acc += w4.z * hs[(k + 2) * 32 + b];
            acc += w4.w * hs[(k + 3) * 32 + b];
        }
    }
    float m = acc;
#pragma unroll
    for (int o = 16; o; o >>= 1) m = fmaxf(m, __shfl_xor_sync(0xffffffffu, m, o));
    float e = expf(acc - m);
    float ssum = e;
#pragma unroll
    for (int o = 16; o; o >>= 1) ssum += __shfl_xor_sync(0xffffffffu, ssum, o);
    ps[j][b] = e / ssum;
    __syncthreads();

    if (tid < 96) {
        int b2 = tid / 3, i = tid - b2 * 3;
        float ssin = 0.f, scos = 0.f;
#pragma unroll
        for (int jj = 0; jj < 20; jj++) {
            float p = ps[jj][b2];
            ssin += p * sa[jj * 3 + i];
            scos += p * ca[jj * 3 + i];
        }
        g_ang[l * 96 + b2 * 3 + i] = atan2f(ssin, scos);
    }
}

// =============================================================================
// NeRF backbone extension (unchanged).
// =============================================================================
__global__ void nerf_kernel(float* __restrict__ out)
{
    int b = threadIdx.x;
    float ax = 0.f,   ay = 0.f,   az = 0.f;
    float bx = 100.f, by = 0.f,   bz = 0.f;
    float cx = 200.f, cy = 100.f, cz = 0.f;

    const float BL0 = 145.801f, BL1 = 152.326f, BL2 = 132.868f;
    const float TH0 = 2.124f,   TH1 = 1.941f,   TH2 = 2.028f;
    float d0a = -BL0 * cosf(TH0), d1a = BL0 * sinf(TH0);
    float d0b = -BL1 * cosf(TH1), d1b = BL1 * sinf(TH1);
    float d0c = -BL2 * cosf(TH2), d1c = BL2 * sinf(TH2);

    for (int s = 0; s < NCOORD; s++) {
        float phi = g_ang[s * 32 + b];
        int m = s - (s / 3) * 3;
        float d0 = (m == 0) ? d0a : (m == 1) ? d0b : d0c;
        float rs = (m == 0) ? d1a : (m == 1) ? d1b : d1c;

        float vx = cx - bx, vy = cy - by, vz = cz - bz;
        float inv = 1.f / (sqrtf(vx * vx + vy * vy + vz * vz) + 1e-12f);
        float bcx = vx * inv, bcy = vy * inv, bcz = vz * inv;

        float ux = bx - ax, uy = by - ay, uz = bz - az;
        float nx = uy * bcz - uz * bcy;
        float ny = uz * bcx - ux * bcz;
        float nz = ux * bcy - uy * bcx;
        float invn = 1.f / (sqrtf(nx * nx + ny * ny + nz * nz) + 1e-12f);
        nx *= invn; ny *= invn; nz *= invn;

        float mx = ny * bcz - nz * bcy;
        float my = nz * bcx - nx * bcz;
        float mz = nx * bcy - ny * bcx;

        float sp, cp;
        sincosf(phi, &sp, &cp);
        float d1 = rs * cp, d2 = rs * sp;

        float dx = cx + d0 * bcx + d1 * mx + d2 * nx;
        float dy = cy + d0 * bcy + d1 * my + d2 * ny;
        float dz = cz + d0 * bcz + d1 * mz + d2 * nz;

        out[s * 96 + b * 3 + 0] = dx;
        out[s * 96 + b * 3 + 1] = dy;
        out[s * 96 + b * 3 + 2] = dz;

        ax = bx; ay = by; az = bz;
        bx = cx; by = cy; bz = cz;
        cx = dx; cy = dy; cz = dz;
    }
}

// =============================================================================
extern "C" void kernel_launch(void* const* d_in, const int* in_sizes, int n_in,
                              void* d_out, int out_size)
{
    const float* x     = (const float*)d_in[0];
    const float* wih0  = (const float*)d_in[1];
    const float* whh0  = (const float*)d_in[2];
    const float* bih0  = (const float*)d_in[3];
    const float* bhh0  = (const float*)d_in[4];
    const float* wih1  = (const float*)d_in[5];
    const float* whh1  = (const float*)d_in[6];
    const float* bih1  = (const float*)d_in[7];
    const float* bhh1  = (const float*)d_in[8];
    const float* wlin  = (const float*)d_in[9];
    const float* blin  = (const float*)d_in[10];
    const float* alpha = (const float*)d_in[11];
    float* out = (float*)d_out;

    static int attr_done = 0;
    if (!attr_done) {
        cudaFuncSetAttribute(lstm_persist,
                             cudaFuncAttributeMaxDynamicSharedMemorySize, SMEM_LSTM);
        cudaFuncSetAttribute(gemm1_mma,
                             cudaFuncAttributeMaxDynamicSharedMemorySize, MM_SMEM);
        attr_done = 1;
    }

    float* G0p; cudaGetSymbolAddress((void**)&G0p, g_G0);
    float* G1p; cudaGetSymbolAddress((void**)&G1p, g_G1);

    // fp16 conversions for layer 0 GEMM
    conv_x<<<2100, 256>>>(x);
    conv_w0<<<600, 256>>>(wih0);

    // Layer 0 input-side pre-activations via fp16 MMA (K=48)
    gemm0_mma<<<dim3(50, 175), 256>>>(bih0, bhh0, G0p);

    // Weight conversion for layer-1 GEMM
    conv_w<<<20000, 256>>>(wih1);

    // Layer 0 recurrence (writes fp16 h directly into gemm1's A operand)
    lstm_persist<<<100, 512, SMEM_LSTM>>>(whh0, 0);

    // Layer 1 input-side pre-activations via fp16 MMA
    gemm1_mma<<<dim3(50, 175), 256, MM_SMEM>>>(bih1, bhh1, G1p);

    // Layer 1 recurrence
    lstm_persist<<<100, 512, SMEM_LSTM>>>(whh1, 1);

    // Head: linear -> softmax(batch dim) -> angles
    head_kernel<<<LSEQ, 640>>>(wlin, blin, alpha);

    // NeRF extension -> output coords [2100][32][3]
    nerf_kernel<<<1, 32>>>(out);
}

// round 16
// speedup vs baseline: 1.1361x; 1.1361x over previous
#include <cuda_runtime.h>
#include <cuda_fp16.h>
#include <math.h>
#include <stdint.h>

// Problem constants
#define LSEQ 700
#define BATCH 32
#define DIN 41
#define HID 800
#define GATES 3200          // 4*HID
#define H2 1600             // 2*HID
#define NCOORD 2100         // 3*LSEQ

// ---------------- device scratch (allocation-free rule: __device__ globals) ---
__device__ float g_G0[2L * LSEQ * GATES * BATCH];   // [2][700][3200][32]
__device__ float g_G1[2L * LSEQ * GATES * BATCH];
__device__ float g_h1[LSEQ * H2 * BATCH];           // layer-1 h (fp32, for head)
__device__ float g_ang[LSEQ * BATCH * 3];
__device__ unsigned g_cnt[4];
__device__ unsigned g_ack[4];
// fp16 operands
__device__ unsigned short g_Ahi16[22400L * 1600];   // h0 fp16 [row=t*32+b][k]
__device__ unsigned g_Bhi[6400 * 800];              // Wih1 fp16 [col][k/2]
__device__ unsigned g_X16[22400L * 24];             // x fp16 [row][k/2] (K=41->48)
__device__ unsigned g_B016[6400 * 24];              // Wih0 fp16 [col][k/2]
// fp16 h state for recurrence MMA: [dir][batch][k]
__device__ unsigned short g_hbf16[2 * 32 * 800];

// ---------------- fp16 helpers -------------------------------------------------
__device__ __forceinline__ unsigned packh2(float a, float b)
{
    __half2 h = __floats2half2_rn(a, b);
    return *(unsigned*)&h;
}
__device__ __forceinline__ void st_u16_cg(unsigned short* p, unsigned short v)
{
    asm volatile("st.global.cg.u16 [%0], %1;" :: "l"(p), "h"(v) : "memory");
}
__device__ __forceinline__ float sigf(float x) { return 1.f / (1.f + expf(-x)); }

// ---------------- warp MMA fp16 ------------------------------------------------
__device__ __forceinline__ void mma16816h(float* d, const unsigned* a,
                                          const unsigned* b)
{
    asm volatile(
        "mma.sync.aligned.m16n8k16.row.col.f32.f16.f16.f32 "
        "{%0,%1,%2,%3}, {%4,%5,%6,%7}, {%8,%9}, {%0,%1,%2,%3};"
        : "+f"(d[0]), "+f"(d[1]), "+f"(d[2]), "+f"(d[3])
        : "r"(a[0]), "r"(a[1]), "r"(a[2]), "r"(a[3]), "r"(b[0]), "r"(b[1]));
}

// =============================================================================
// conv_x: x [32][700][41] f32 -> g_X16 [row=t*32+b][kp<24] fp16 pairs (pad 48).
// =============================================================================
__global__ __launch_bounds__(256)
void conv_x(const float* __restrict__ x)
{
    long i = (long)blockIdx.x * 256 + threadIdx.x;
    if (i >= 22400L * 24) return;
    int row = (int)(i / 24), kp = (int)(i % 24);
    int t = row >> 5, b = row & 31;
    int k0 = 2 * kp, k1 = 2 * kp + 1;
    float v0 = (k0 < DIN) ? x[((long)b * LSEQ + t) * DIN + k0] : 0.f;
    float v1 = (k1 < DIN) ? x[((long)b * LSEQ + t) * DIN + k1] : 0.f;
    g_X16[i] = packh2(v0, v1);
}

// =============================================================================
// conv_w0: Wih0 [2][3200][41] f32 -> g_B016 [col=dir*3200+j][kp<24] fp16 pairs.
// =============================================================================
__global__ __launch_bounds__(256)
void conv_w0(const float* __restrict__ W)
{
    long i = (long)blockIdx.x * 256 + threadIdx.x;
    if (i >= 6400L * 24) return;
    int col = (int)(i / 24), kp = (int)(i % 24);
    int k0 = 2 * kp, k1 = 2 * kp + 1;
    float v0 = (k0 < DIN) ? W[(long)col * DIN + k0] : 0.f;
    float v1 = (k1 < DIN) ? W[(long)col * DIN + k1] : 0.f;
    g_B016[i] = packh2(v0, v1);
}

// =============================================================================
// conv_w: Wih1 [6400][1600] f32 -> fp16 packed pairs [6400][800].
// =============================================================================
__global__ __launch_bounds__(256)
void conv_w(const float* __restrict__ W)
{
    long i = (long)blockIdx.x * 256 + threadIdx.x;
    if (i >= 6400L * 800) return;
    float2 v = *(const float2*)(W + 2 * i);
    g_Bhi[i] = packh2(v.x, v.y);
}

// =============================================================================
// gemm0_mma: G0 = x @ Wih0^T + biases via fp16 warp MMA (K=48, one chunk).
// =============================================================================
#define M0STR 28
__global__ __launch_bounds__(256, 2)
void gemm0_mma(const float* __restrict__ bias1, const float* __restrict__ bias2,
               float* __restrict__ Gout)
{
    __shared__ unsigned As[128 * M0STR];
    __shared__ unsigned Bs[128 * M0STR];

    int tid = threadIdx.x;
    int wid = tid >> 5, lane = tid & 31;
    int g = lane >> 2, tig = lane & 3;
    int col0 = blockIdx.x * 128;
    int row0 = blockIdx.y * 128;
    int m0 = (wid & 3) * 32;
    int n0 = (wid >> 2) * 64;

    for (int i = tid; i < 128 * 24; i += 256) {
        int r = i / 24, kp = i % 24;
        As[r * M0STR + kp] = g_X16[(long)(row0 + r) * 24 + kp];
        Bs[r * M0STR + kp] = g_B016[(long)(col0 + r) * 24 + kp];
    }
    __syncthreads();

    float acc[2][8][4];
#pragma unroll
    for (int mt = 0; mt < 2; mt++)
#pragma unroll
        for (int nt = 0; nt < 8; nt++)
#pragma unroll
            for (int q = 0; q < 4; q++) acc[mt][nt][q] = 0.f;

#pragma unroll
    for (int kk = 0; kk < 3; kk++) {
        int kpb = kk * 8;
        unsigned bh[8][2];
#pragma unroll
        for (int nt = 0; nt < 8; nt++) {
            int br = (n0 + nt * 8 + g) * M0STR + kpb + tig;
            bh[nt][0] = Bs[br];     bh[nt][1] = Bs[br + 4];
        }
#pragma unroll
        for (int mt = 0; mt < 2; mt++) {
            int ar0 = (m0 + mt * 16 + g) * M0STR + kpb + tig;
            int ar1 = ar0 + 8 * M0STR;
            unsigned ah[4] = { As[ar0], As[ar1], As[ar0 + 4], As[ar1 + 4] };
#pragma unroll
            for (int nt = 0; nt < 8; nt++)
                mma16816h(acc[mt][nt], ah, bh[nt]);
        }
    }

#pragma unroll
    for (int mt = 0; mt < 2; mt++) {
        int r0 = row0 + m0 + mt * 16 + g;
        int r1 = r0 + 8;
        int t0 = r0 >> 5, b0 = r0 & 31;
        int t1 = r1 >> 5, b1 = r1 & 31;
#pragma unroll
        for (int nt = 0; nt < 8; nt++) {
            int c0 = col0 + n0 + nt * 8 + 2 * tig;
#pragma unroll
            for (int q = 0; q < 2; q++) {
                int col = c0 + q;
                int dir = (col >= GATES) ? 1 : 0;
                int j = col - dir * GATES;
                float bb = bias1[col] + bias2[col];
                Gout[((long)(dir * LSEQ + t0) * GATES + j) * BATCH + b0] =
                    acc[mt][nt][q] + bb;
                Gout[((long)(dir * LSEQ + t1) * GATES + j) * BATCH + b1] =
                    acc[mt][nt][2 + q] + bb;
            }
        }
    }
}

// =============================================================================
// gemm1_mma: G1 = h0 @ Wih1^T + biases via pure fp16 warp MMA (R14 verbatim).
// =============================================================================
#define MM_STRIDE 36
#define MM_ASZ (128 * MM_STRIDE)
#define MM_SMEM (2 * MM_ASZ * 4)                    // 36864 bytes

__global__ __launch_bounds__(256, 2)
void gemm1_mma(const float* __restrict__ bias1, const float* __restrict__ bias2,
               float* __restrict__ Gout)
{
    extern __shared__ unsigned sm[];
    unsigned* Ah = sm;
    unsigned* Bh = Ah + MM_ASZ;

    const unsigned* Asrc = (const unsigned*)g_Ahi16;

    int tid = threadIdx.x;
    int wid = tid >> 5, lane = tid & 31;
    int g = lane >> 2, tig = lane & 3;
    int col0 = blockIdx.x * 128;
    int row0 = blockIdx.y * 128;
    int m0 = (wid & 3) * 32;
    int n0 = (wid >> 2) * 64;

    float acc[2][8][4];
#pragma unroll
    for (int mt = 0; mt < 2; mt++)
#pragma unroll
        for (int nt = 0; nt < 8; nt++)
#pragma unroll
            for (int q = 0; q < 4; q++) acc[mt][nt][q] = 0.f;

    int sr = tid >> 4, skq = tid & 15;

    for (int ch = 0; ch < 25; ch++) {
        __syncthreads();
#pragma unroll
        for (int it = 0; it < 8; it++) {
            int rr = sr + it * 16;
            long ao = (long)(row0 + rr) * 800 + ch * 32 + 2 * skq;
            long bo = (long)(col0 + rr) * 800 + ch * 32 + 2 * skq;
            *(uint2*)(Ah + rr * MM_STRIDE + 2 * skq) = *(const uint2*)(Asrc + ao);
            *(uint2*)(Bh + rr * MM_STRIDE + 2 * skq) = *(const uint2*)(g_Bhi + bo);
        }
        __syncthreads();

#pragma unroll
        for (int kk = 0; kk < 4; kk++) {
            int kpb = kk * 8;
            unsigned bh[8][2];
#pragma unroll
            for (int nt = 0; nt < 8; nt++) {
                int br = (n0 + nt * 8 + g) * MM_STRIDE + kpb + tig;
                bh[nt][0] = Bh[br];     bh[nt][1] = Bh[br + 4];
            }
#pragma unroll
            for (int mt = 0; mt < 2; mt++) {
                int ar0 = (m0 + mt * 16 + g) * MM_STRIDE + kpb + tig;
                int ar1 = ar0 + 8 * MM_STRIDE;
                unsigned ah[4] = { Ah[ar0], Ah[ar1], Ah[ar0 + 4], Ah[ar1 + 4] };
#pragma unroll
                for (int nt = 0; nt < 8; nt++)
                    mma16816h(acc[mt][nt], ah, bh[nt]);
            }
        }
    }

#pragma unroll
    for (int mt = 0; mt < 2; mt++) {
        int r0 = row0 + m0 + mt * 16 + g;
        int r1 = r0 + 8;
        int t0 = r0 >> 5, b0 = r0 & 31;
        int t1 = r1 >> 5, b1 = r1 & 31;
#pragma unroll
        for (int nt = 0; nt < 8; nt++) {
            int c0 = col0 + n0 + nt * 8 + 2 * tig;
#pragma unroll
            for (int q = 0; q < 2; q++) {
                int col = c0 + q;
                int dir = (col >= GATES) ? 1 : 0;
                int j = col - dir * GATES;
                float bb = bias1[col] + bias2[col];
                Gout[((long)(dir * LSEQ + t0) * GATES + j) * BATCH + b0] =
                    acc[mt][nt][q] + bb;
                Gout[((long)(dir * LSEQ + t1) * GATES + j) * BATCH + b1] =
                    acc[mt][nt][2 + q] + bb;
            }
        }
    }
}

// =============================================================================
// Persistent bidirectional LSTM recurrence — R14 VERBATIM (proven 10.99ms).
// Pure fp16 MMA (1 pass), 512 threads / 16 warps; full h staged in one chunk.
// =============================================================================
#define NCTA_DIR 50
#define WSTR 404
#define LS_WW (64 * WSTR)
#define LS_BS_OFF (LS_WW * 4)                   // 103424
#define LS_BW (32 * WSTR)
#define LS_PB_OFF (LS_BS_OFF + LS_BW * 4)       // 155136
#define SMEM_LSTM (LS_PB_OFF + 2 * 64 * 32 * 4) // 171520 bytes

__global__ __launch_bounds__(512, 1)
void lstm_persist(const float* __restrict__ Whh, int layer)
{
    extern __shared__ char smemc[];
    unsigned* wsH = (unsigned*)smemc;                  // [64][WSTR] fp16 pairs
    unsigned* bs  = (unsigned*)(smemc + LS_BS_OFF);    // [32][WSTR] fp16 h pairs
    float* pb = (float*)(smemc + LS_PB_OFF);           // [2][64][32]

    const float* G = layer ? g_G1 : g_G0;

    int c   = blockIdx.x;
    int dir = c / NCTA_DIR;
    int ubase = (c % NCTA_DIR) * 16;
    int tid = threadIdx.x;
    int wid = tid >> 5, lane = tid & 31;
    int gate  = wid & 3;
    int khalf = (wid >> 2) & 1;
    int nhalf = wid >> 3;
    int g = lane >> 2, tig = lane & 3;
    int cb = lane;
    int lu = wid;
    int u  = ubase + lu;

    unsigned short* hb16 = g_hbf16 + dir * 32 * 800;   // [32][800]
    const unsigned* hb = (const unsigned*)hb16;        // [32][400] pair view

    unsigned* cnt = &g_cnt[layer * 2 + dir];
    unsigned* ack = &g_ack[layer * 2 + dir];

    // ---- convert Whh slice -> smem fp16 (once) ----
    const float* Wd = Whh + (long)dir * GATES * HID;
    for (int i = tid; i < 64 * 400; i += 512) {
        int r = i / 400, kp = i % 400;
        int grow = (r >> 4) * HID + ubase + (r & 15);
        float v0 = Wd[(long)grow * HID + 2 * kp];
        float v1 = Wd[(long)grow * HID + 2 * kp + 1];
        wsH[r * WSTR + kp] = packh2(v0, v1);
    }
    __syncthreads();

    float creg = 0.f;

    for (int s = 0; s < LSEQ; s++) {
        int t = dir ? (LSEQ - 1 - s) : s;

        // gate pre-activations (cell mapping), issued early
        long gb = ((long)(dir * LSEQ + t)) * GATES * BATCH;
        float gp[4];
#pragma unroll
        for (int g4 = 0; g4 < 4; g4++)
            gp[g4] = G[gb + (long)(g4 * HID + u) * BATCH + cb];

        float ds[4] = {0.f, 0.f, 0.f, 0.f};

        if (s > 0) {
            // ---- stage FULL h (32 x 400 pair-words) in one shot ----
            __syncthreads();                           // bs free (prev MMA done)
#pragma unroll
            for (int ii = 0; ii < 25; ii++) {
                int i = tid + 512 * ii;
                int b = i / 400, kp = i - b * 400;
                bs[b * WSTR + kp] = __ldcg(hb + i);
            }
            __syncthreads();                           // bs ready

            float acc[2][4];
#pragma unroll
            for (int ntl = 0; ntl < 2; ntl++)
#pragma unroll
                for (int q = 0; q < 4; q++) acc[ntl][q] = 0.f;

#pragma unroll
            for (int ki = 0; ki < 25; ki++) {
                int kk = khalf * 25 + ki;
                int akp = kk * 8 + tig;
                int ar0 = (gate * 16 + g) * WSTR + akp;
                int ar1 = ar0 + 8 * WSTR;
                unsigned ah[4] = { wsH[ar0], wsH[ar1], wsH[ar0+4], wsH[ar1+4] };
#pragma unroll
                for (int ntl = 0; ntl < 2; ntl++) {
                    int nt = nhalf * 2 + ntl;
                    int br = (nt * 8 + g) * WSTR + akp;
                    unsigned bfr[2] = { bs[br], bs[br + 4] };
                    mma16816h(acc[ntl], ah, bfr);
                }
            }

            // publish partials (pb separate buffer)
            {
                float* pbW = pb + khalf * (64 * 32);
#pragma unroll
                for (int ntl = 0; ntl < 2; ntl++) {
                    int colb = (nhalf * 2 + ntl) * 8 + 2 * tig;
                    pbW[(gate * 16 + g) * 32 + colb]         = acc[ntl][0];
                    pbW[(gate * 16 + g) * 32 + colb + 1]     = acc[ntl][1];
                    pbW[(gate * 16 + g + 8) * 32 + colb]     = acc[ntl][2];
                    pbW[(gate * 16 + g + 8) * 32 + colb + 1] = acc[ntl][3];
                }
            }
            __syncthreads();                           // pb ready
#pragma unroll
            for (int g4 = 0; g4 < 4; g4++) {
                int r = (g4 * 16 + lu) * 32 + cb;
                ds[g4] = pb[r] + pb[64 * 32 + r];
            }
        }

        // ---- LSTM cell (one unit) ----
        float ai = gp[0] + ds[0];
        float af = gp[1] + ds[1];
        float ag = gp[2] + ds[2];
        float ao = gp[3] + ds[3];

        creg = sigf(af) * creg + sigf(ai) * tanhf(ag);
        float hv = sigf(ao) * tanhf(creg);

        if (layer) {
            __stcg(g_h1 + ((long)t * H2 + dir * HID + u) * BATCH + cb, hv);
        } else {
            st_u16_cg(g_Ahi16 + ((long)(t * 32 + cb) * 1600 + dir * 800 + u),
                      __half_as_ushort(__float2half_rn(hv)));
        }
        st_u16_cg(hb16 + cb * 800 + u, __half_as_ushort(__float2half_rn(hv)));

        // ---- grid barrier over this direction's 50 CTAs ----
        __syncthreads();
        if (tid == 0) {
            asm volatile("red.release.gpu.global.add.u32 [%0], %1;"
                         :: "l"(cnt), "r"(1u) : "memory");
            unsigned target = (unsigned)(s + 1) * NCTA_DIR;
            unsigned v;
            do {
                asm volatile("ld.acquire.gpu.global.u32 %0, [%1];"
                             : "=r"(v) : "l"(cnt) : "memory");
            } while (v < target);
        }
        __syncthreads();
    }

    // ---- replay-safe counter reset via ack ----
    if (tid == 0) {
        asm volatile("red.release.gpu.global.add.u32 [%0], %1;"
                     :: "l"(ack), "r"(1u) : "memory");
        if ((c % NCTA_DIR) == 0) {
            unsigned v;
            do {
                asm volatile("ld.acquire.gpu.global.u32 %0, [%1];"
                             : "=r"(v) : "l"(ack) : "memory");
            } while (v < NCTA_DIR);
            *cnt = 0;
            *ack = 0;
            __threadfence();
        }
    }
}

// =============================================================================
// Fused head (k-chunk 160): linear -> softmax over BATCH dim -> angles.
// =============================================================================
#define HCHUNK 160
__global__ __launch_bounds__(640)
void head_kernel(const float* __restrict__ wlin, const float* __restrict__ blin,
                 const float* __restrict__ alphabet)
{
    int l = blockIdx.x;
    int tid = threadIdx.x;
    int j = tid >> 5, b = tid & 31;

    __shared__ float hs[HCHUNK * 32];
    __shared__ float ps[20][32];
    __shared__ float sa[60], ca[60];

    if (tid < 60) { float v = alphabet[tid]; sa[tid] = sinf(v); ca[tid] = cosf(v); }

    float acc = blin[j];
    const float* hb = g_h1 + (long)l * (H2 * BATCH);
    const float* w = wlin + j * H2;
    for (int k0 = 0; k0 < H2; k0 += HCHUNK) {
        __syncthreads();
#pragma unroll
        for (int i = 0; i < (HCHUNK * 32) / 640; i++)
            hs[tid + 640 * i] = hb[k0 * 32 + tid + 640 * i];
        __syncthreads();
#pragma unroll 8
        for (int k = 0; k < HCHUNK; k += 4) {
            float4 w4 = *(const float4*)(w + k0 + k);
            acc += w4.x * hs[(k + 0) * 32 + b];
            acc += w4.y * hs[(k + 1) * 32 + b];
            acc += w4.z * hs[(k + 2) * 32 + b];
            acc += w4.w * hs[(k + 3) * 32 + b];
        }
    }
    float m = acc;
#pragma unroll
    for (int o = 16; o; o >>= 1) m = fmaxf(m, __shfl_xor_sync(0xffffffffu, m, o));
    float e = expf(acc - m);
    float ssum = e;
#pragma unroll
    for (int o = 16; o; o >>= 1) ssum += __shfl_xor_sync(0xffffffffu, ssum, o);
    ps[j][b] = e / ssum;
    __syncthreads();

    if (tid < 96) {
        int b2 = tid / 3, i = tid - b2 * 3;
        float ssin = 0.f, scos = 0.f;
#pragma unroll
        for (int jj = 0; jj < 20; jj++) {
            float p = ps[jj][b2];
            ssin += p * sa[jj * 3 + i];
            scos += p * ca[jj * 3 + i];
        }
        g_ang[l * 96 + b2 * 3 + i] = atan2f(ssin, scos);
    }
}

// =============================================================================
// NeRF backbone extension (unchanged).
// =============================================================================
__global__ void nerf_kernel(float* __restrict__ out)
{
    int b = threadIdx.x;
    float ax = 0.f,   ay = 0.f,   az = 0.f;
    float bx = 100.f, by = 0.f,   bz = 0.f;
    float cx = 200.f, cy = 100.f, cz = 0.f;

    const float BL0 = 145.801f, BL1 = 152.326f, BL2 = 132.868f;
    const float TH0 = 2.124f,   TH1 = 1.941f,   TH2 = 2.028f;
    float d0a = -BL0 * cosf(TH0), d1a = BL0 * sinf(TH0);
    float d0b = -BL1 * cosf(TH1), d1b = BL1 * sinf(TH1);
    float d0c = -BL2 * cosf(TH2), d1c = BL2 * sinf(TH2);

    for (int s = 0; s < NCOORD; s++) {
        float phi = g_ang[s * 32 + b];
        int m = s - (s / 3) * 3;
        float d0 = (m == 0) ? d0a : (m == 1) ? d0b : d0c;
        float rs = (m == 0) ? d1a : (m == 1) ? d1b : d1c;

        float vx = cx - bx, vy = cy - by, vz = cz - bz;
        float inv = 1.f / (sqrtf(vx * vx + vy * vy + vz * vz) + 1e-12f);
        float bcx = vx * inv, bcy = vy * inv, bcz = vz * inv;

        float ux = bx - ax, uy = by - ay, uz = bz - az;
        float nx = uy * bcz - uz * bcy;
        float ny = uz * bcx - ux * bcz;
        float nz = ux * bcy - uy * bcx;
        float invn = 1.f / (sqrtf(nx * nx + ny * ny + nz * nz) + 1e-12f);
        nx *= invn; ny *= invn; nz *= invn;

        float mx = ny * bcz - nz * bcy;
        float my = nz * bcx - nx * bcz;
        float mz = nx * bcy - ny * bcx;

        float sp, cp;
        sincosf(phi, &sp, &cp);
        float d1 = rs * cp, d2 = rs * sp;

        float dx = cx + d0 * bcx + d1 * mx + d2 * nx;
        float dy = cy + d0 * bcy + d1 * my + d2 * ny;
        float dz = cz + d0 * bcz + d1 * mz + d2 * nz;

        out[s * 96 + b * 3 + 0] = dx;
        out[s * 96 + b * 3 + 1] = dy;
        out[s * 96 + b * 3 + 2] = dz;

        ax = bx; ay = by; az = bz;
        bx = cx; by = cy; bz = cz;
        cx = dx; cy = dy; cz = dz;
    }
}

// =============================================================================
extern "C" void kernel_launch(void* const* d_in, const int* in_sizes, int n_in,
                              void* d_out, int out_size)
{
    const float* x     = (const float*)d_in[0];
    const float* wih0  = (const float*)d_in[1];
    const float* whh0  = (const float*)d_in[2];
    const float* bih0  = (const float*)d_in[3];
    const float* bhh0  = (const float*)d_in[4];
    const float* wih1  = (const float*)d_in[5];
    const float* whh1  = (const float*)d_in[6];
    const float* bih1  = (const float*)d_in[7];
    const float* bhh1  = (const float*)d_in[8];
    const float* wlin  = (const float*)d_in[9];
    const float* blin  = (const float*)d_in[10];
    const float* alpha = (const float*)d_in[11];
    float* out = (float*)d_out;

    static int attr_done = 0;
    if (!attr_done) {
        cudaFuncSetAttribute(lstm_persist,
                             cudaFuncAttributeMaxDynamicSharedMemorySize, SMEM_LSTM);
        cudaFuncSetAttribute(gemm1_mma,
                             cudaFuncAttributeMaxDynamicSharedMemorySize, MM_SMEM);
        attr_done = 1;
    }

    float* G0p; cudaGetSymbolAddress((void**)&G0p, g_G0);
    float* G1p; cudaGetSymbolAddress((void**)&G1p, g_G1);

    // fp16 conversions for layer 0 GEMM
    conv_x<<<2100, 256>>>(x);
    conv_w0<<<600, 256>>>(wih0);

    // Layer 0 input-side pre-activations via fp16 MMA (K=48)
    gemm0_mma<<<dim3(50, 175), 256>>>(bih0, bhh0, G0p);

    // Weight conversion for layer-1 GEMM
    conv_w<<<20000, 256>>>(wih1);

    // Layer 0 recurrence (writes fp16 h directly into gemm1's A operand)
    lstm_persist<<<100, 512, SMEM_LSTM>>>(whh0, 0);

    // Layer 1 input-side pre-activations via fp16 MMA
    gemm1_mma<<<dim3(50, 175), 256, MM_SMEM>>>(bih1, bhh1, G1p);

    // Layer 1 recurrence
    lstm_persist<<<100, 512, SMEM_LSTM>>>(whh1, 1);

    // Head: linear -> softmax(batch dim) -> angles
    head_kernel<<<LSEQ, 640>>>(wlin, blin, alpha);

    // NeRF extension -> output coords [2100][32][3]
    nerf_kernel<<<1, 32>>>(out);
}